// round 4
// baseline (speedup 1.0000x reference)
#include <cuda_runtime.h>
#include <cstdint>

// Problem constants
#define NB   64
#define NT   2048
#define EMBD 32
#define HID  256
#define KTOT (EMBD + HID)    // 288
#define USLICE 32
#define BSLICE 4
#define NCTA  (USLICE * BSLICE)   // 128
#define UPC   8              // units per CTA
#define NROWS (4 * UPC)      // 32 gate rows
#define BPC   16             // batches per CTA
#define NTHREADS 256         // 8 warps -> 2 per SMSP

#define WPAD 296             // floats; 296%32==8 -> 4 rows/warp on banks 0/8/16/24; 1184B (16B-aligned)
#define ZPAD 292             // floats; 292%32==4 -> 8 batch rows on banks 0/4/..28; 1168B (16B-aligned)

// Persistent cross-CTA state
__device__ float g_H[2][NB * HID];   // [buf][batch*HID + unit]
__device__ unsigned g_count;
__device__ volatile unsigned g_release;

__global__ void lstm_init_kernel() { g_count = 0u; g_release = 0u; }

__device__ __forceinline__ float sigf(float x)  { return 1.0f / (1.0f + __expf(-x)); }
__device__ __forceinline__ float tanha(float x) { return 2.0f / (1.0f + __expf(-2.0f * x)) - 1.0f; }

#define LDS2U64(a, b, addr) \
    asm volatile("ld.shared.v2.u64 {%0,%1}, [%2];" : "=l"(a), "=l"(b) : "r"(addr))
#define FMA2(acc, w, z) \
    asm volatile("fma.rn.f32x2 %0, %1, %2, %0;" : "+l"(acc) : "l"(w), "l"(z))

__global__ void __launch_bounds__(NTHREADS, 1)
lstm_persist_kernel(const int* __restrict__ x,
                    const int* __restrict__ lengths,
                    const float* __restrict__ emb,
                    const float* __restrict__ W_ih,
                    const float* __restrict__ W_hh,
                    const float* __restrict__ b_ih,
                    const float* __restrict__ b_hh,
                    float* __restrict__ out)
{
    extern __shared__ float sm[];
    float* w_s  = sm;                         // [NROWS][WPAD]
    float* z_s  = w_s + NROWS * WPAD;         // [BPC][ZPAD]  (k: 0..31 xe, 32..287 h)
    float* gs   = z_s + BPC * ZPAD;           // [NROWS][BPC]
    float* bs   = gs + NROWS * BPC;           // [NROWS]
    int* lenS   = (int*)(bs + NROWS);         // [NB]
    int* mlS    = lenS + NB;

    const int tid = threadIdx.x;
    const int cta = blockIdx.x;
    const int us  = cta >> 2;
    const int bsl = cta & 3;
    const int u0  = us * UPC;
    const int bb0 = bsl * BPC;

    // ---- one-time staging ----
    for (int idx = tid; idx < NROWS * KTOT; idx += NTHREADS) {
        int r = idx / KTOT;
        int k = idx - r * KTOT;
        int g = r >> 3, du = r & 7;
        int grow = g * HID + u0 + du;
        float v = (k < EMBD) ? W_ih[grow * EMBD + k]
                             : W_hh[grow * HID + (k - EMBD)];
        w_s[r * WPAD + k] = v;
    }
    if (tid < NROWS) {
        int g = tid >> 3, du = tid & 7;
        int grow = g * HID + u0 + du;
        bs[tid] = b_ih[grow] + b_hh[grow];
    }
    if (tid < NB) lenS[tid] = lengths[tid];
    __syncthreads();
    if (tid == 0) {
        int m = 1;
        for (int b = 0; b < NB; b++) m = max(m, lenS[b]);
        *mlS = m;
    }
    // zero h region of z (t=0)
    for (int i = tid; i < BPC * HID; i += NTHREADS) {
        int b = i >> 8, u = i & 255;
        z_s[b * ZPAD + EMBD + u] = 0.0f;
    }
    // gather xe(0)
    if (tid < BPC) {
        int tok = x[(bb0 + tid) * NT + 0];
        const float4* e = (const float4*)(emb + (long)tok * EMBD);
        float4* zr = (float4*)(z_s + tid * ZPAD);
        #pragma unroll
        for (int q = 0; q < EMBD / 4; q++) zr[q] = e[q];
    }
    __syncthreads();
    const int maxlen = *mlS;

    // shared base address for asm
    uint32_t sb;
    asm("{ .reg .u64 t; cvta.to.shared.u64 t, %1; cvt.u32.u64 %0, t; }"
        : "=r"(sb) : "l"(sm));
    const uint32_t ZOFF = (uint32_t)(NROWS * WPAD) * 4u;

    // GEMM mapping: 256 threads = 32 rows x 8 batch-slots; batches bp and bp+8
    const int row = tid >> 3;          // 0..31
    const int bp  = tid & 7;           // 0..7 -> batches bp, bp+8
    const uint32_t waddr0 = sb + (uint32_t)(row * WPAD) * 4u;
    const uint32_t zaddrA = sb + ZOFF + (uint32_t)(bp * ZPAD) * 4u;
    const uint32_t zaddrB = zaddrA + (uint32_t)(8 * ZPAD) * 4u;
    const float bias = bs[row];
    float* goutA = gs + row * BPC + bp;
    float* goutB = goutA + 8;

    // phase-2 mapping (tid < 128): one (unit,batch)
    const int du2 = tid >> 4;          // 0..7 (valid when tid<128)
    const int b2l = tid & 15;
    const int bg = bb0 + b2l;
    const int uu = u0 + (du2 & 7);
    const int mylen = lenS[bg];
    float c_r = 0.0f, h_r = 0.0f;

    unsigned long long Aa, Ab;
    const unsigned long long bias_pk =
        (unsigned long long)__float_as_uint(bias);   // (bias, 0) packed

    // ---- prologue: acc = bias + W_ih . xe(0) ----
    Aa = bias_pk; Ab = bias_pk;
    #pragma unroll
    for (int k = 0; k < EMBD; k += 4) {
        unsigned long long W01, W23, Z01a, Z23a, Z01b, Z23b;
        LDS2U64(W01, W23, waddr0 + k * 4);
        LDS2U64(Z01a, Z23a, zaddrA + k * 4);
        LDS2U64(Z01b, Z23b, zaddrB + k * 4);
        FMA2(Aa, W01, Z01a); FMA2(Ab, W01, Z01b);
        FMA2(Aa, W23, Z23a); FMA2(Ab, W23, Z23b);
    }

    for (int t = 0; t < maxlen; t++) {
        // ---- stage h(t-1): g_H[t&1][b][u] -> z_s[b][32+u] ----
        if (t > 0) {
            const float4* src = (const float4*)(g_H[t & 1] + bb0 * HID);
            #pragma unroll
            for (int i = 0; i < (BPC * HID / 4) / NTHREADS; i++) {
                int idx = i * NTHREADS + tid;       // 0..1023
                int b = idx >> 6;                   // 0..15
                int u4 = (idx & 63) * 4;            // 0..252
                float4 v = src[idx];
                *(float4*)(z_s + b * ZPAD + EMBD + u4) = v;
            }
        }
        __syncthreads();

        // ---- acc += W_hh . h  (k = 32..287), k-split f32x2 ----
        {
            const uint32_t wk = waddr0 + EMBD * 4;
            const uint32_t zkA = zaddrA + EMBD * 4;
            const uint32_t zkB = zaddrB + EMBD * 4;
            #pragma unroll 4
            for (int k = 0; k < HID; k += 4) {
                unsigned long long W01, W23, Z01a, Z23a, Z01b, Z23b;
                LDS2U64(W01, W23, wk + k * 4);
                LDS2U64(Z01a, Z23a, zkA + k * 4);
                LDS2U64(Z01b, Z23b, zkB + k * 4);
                FMA2(Aa, W01, Z01a); FMA2(Ab, W01, Z01b);
                FMA2(Aa, W23, Z23a); FMA2(Ab, W23, Z23b);
            }
        }
        // gate = lo + hi of each accumulator
        {
            float a_lo = __uint_as_float((uint32_t)Aa);
            float a_hi = __uint_as_float((uint32_t)(Aa >> 32));
            float b_lo = __uint_as_float((uint32_t)Ab);
            float b_hi = __uint_as_float((uint32_t)(Ab >> 32));
            *goutA = a_lo + a_hi;
            *goutB = b_lo + b_hi;
        }
        __syncthreads();

        // ---- phase 2: activations + state update (tid < 128) ----
        if (tid < 128) {
            float gi = gs[(0 * UPC + du2) * BPC + b2l];
            float gf = gs[(1 * UPC + du2) * BPC + b2l];
            float gg = gs[(2 * UPC + du2) * BPC + b2l];
            float go = gs[(3 * UPC + du2) * BPC + b2l];
            float iv = sigf(gi), fv = sigf(gf), gv = tanha(gg), ov = sigf(go);
            float cn = fmaf(fv, c_r, iv * gv);
            float hn = ov * tanha(cn);
            if (t < mylen) { c_r = cn; h_r = hn; }
            g_H[(t & 1) ^ 1][bg * HID + uu] = h_r;
        }
        __syncthreads();   // all g_H writes issued

        if (t + 1 < maxlen) {
            // barrier ARRIVE (non-blocking)
            if (tid == 0) {
                __threadfence();
                unsigned old = atomicAdd(&g_count, 1u);
                if (old == NCTA - 1) {
                    atomicExch(&g_count, 0u);
                    __threadfence();
                    g_release = (unsigned)(t + 1);
                }
            }
            // overlap: gather xe(t+1)
            if (tid < BPC) {
                int tok = x[(bb0 + tid) * NT + (t + 1)];
                const float4* e = (const float4*)(emb + (long)tok * EMBD);
                float4* zr = (float4*)(z_s + tid * ZPAD);
                #pragma unroll
                for (int q = 0; q < EMBD / 4; q++) zr[q] = e[q];
            }
            __syncthreads();
            // overlap: input-projection GEMM for t+1
            Aa = bias_pk; Ab = bias_pk;
            #pragma unroll
            for (int k = 0; k < EMBD; k += 4) {
                unsigned long long W01, W23, Z01a, Z23a, Z01b, Z23b;
                LDS2U64(W01, W23, waddr0 + k * 4);
                LDS2U64(Z01a, Z23a, zaddrA + k * 4);
                LDS2U64(Z01b, Z23b, zaddrB + k * 4);
                FMA2(Aa, W01, Z01a); FMA2(Ab, W01, Z01b);
                FMA2(Aa, W23, Z23a); FMA2(Ab, W23, Z23b);
            }
            // barrier WAIT
            if (tid == 0) {
                while (g_release < (unsigned)(t + 1)) { }
                __threadfence();
            }
            __syncthreads();
        }
    }

    if (tid < 128) out[bg * HID + uu] = h_r;
}

extern "C" void kernel_launch(void* const* d_in, const int* in_sizes, int n_in,
                              void* d_out, int out_size) {
    const int*   x       = (const int*)d_in[0];
    const int*   lengths = (const int*)d_in[1];
    const float* emb     = (const float*)d_in[2];
    const float* W_ih    = (const float*)d_in[3];
    const float* W_hh    = (const float*)d_in[4];
    const float* b_ih    = (const float*)d_in[5];
    const float* b_hh    = (const float*)d_in[6];
    float* out = (float*)d_out;

    const int smem_bytes =
        (NROWS * WPAD + BPC * ZPAD + NROWS * BPC + NROWS) * (int)sizeof(float)
        + (NB + 1) * (int)sizeof(int) + 32;

    cudaFuncSetAttribute(lstm_persist_kernel,
                         cudaFuncAttributeMaxDynamicSharedMemorySize, smem_bytes);

    lstm_init_kernel<<<1, 1>>>();
    lstm_persist_kernel<<<NCTA, NTHREADS, smem_bytes>>>(
        x, lengths, emb, W_ih, W_hh, b_ih, b_hh, out);
}

// round 5
// speedup vs baseline: 1.2070x; 1.2070x over previous
#include <cuda_runtime.h>
#include <cstdint>

// Problem constants
#define NB   64
#define NT   2048
#define EMBD 32
#define HID  256
#define KTOT (EMBD + HID)    // 288
#define USLICE 32
#define BSLICE 4
#define NCTA  (USLICE * BSLICE)   // 128
#define UPC   8              // units per CTA
#define NROWS (4 * UPC)      // 32 gate rows
#define BPC   16             // batches per CTA
#define NTHREADS 256         // 8 warps -> 2 per SMSP

#define WPAD 296             // floats; %32==8 -> 4 W rows/warp on banks 0/8/16/24; 16B-aligned
#define ZPAD 292             // floats; %32==4 -> 8 z rows/warp tile all 32 banks; 16B-aligned

// Persistent cross-CTA state
__device__ float g_H[2][NB * HID];     // [buf][batch*HID + unit]
__device__ int   g_flag[BSLICE][USLICE];  // steps completed by producer CTA (us,bsl)

__global__ void lstm_init_kernel() {
    int i = threadIdx.x;
    if (i < BSLICE * USLICE) ((int*)g_flag)[i] = 0;
}

__device__ __forceinline__ float sigf(float x)  { return 1.0f / (1.0f + __expf(-x)); }
__device__ __forceinline__ float tanha(float x) { return 2.0f / (1.0f + __expf(-2.0f * x)) - 1.0f; }

#define LDS2U64(a, b, addr) \
    asm volatile("ld.shared.v2.u64 {%0,%1}, [%2];" : "=l"(a), "=l"(b) : "r"(addr))
#define FMA2(acc, w, z) \
    asm volatile("fma.rn.f32x2 %0, %1, %2, %0;" : "+l"(acc) : "l"(w), "l"(z))

__global__ void __launch_bounds__(NTHREADS, 1)
lstm_persist_kernel(const int* __restrict__ x,
                    const int* __restrict__ lengths,
                    const float* __restrict__ emb,
                    const float* __restrict__ W_ih,
                    const float* __restrict__ W_hh,
                    const float* __restrict__ b_ih,
                    const float* __restrict__ b_hh,
                    float* __restrict__ out)
{
    extern __shared__ float sm[];
    float* w_s  = sm;                         // [NROWS][WPAD]
    float* z_s  = w_s + NROWS * WPAD;         // [BPC][ZPAD]  (k: 0..31 xe, 32..287 h)
    float* gs   = z_s + BPC * ZPAD;           // [NROWS][BPC]
    float* bs   = gs + NROWS * BPC;           // [NROWS]
    int* lenS   = (int*)(bs + NROWS);         // [NB]
    int* mlS    = lenS + NB;

    const int tid = threadIdx.x;
    const int cta = blockIdx.x;
    const int us  = cta >> 2;
    const int bsl = cta & 3;
    const int u0  = us * UPC;
    const int bb0 = bsl * BPC;

    // ---- one-time staging ----
    for (int idx = tid; idx < NROWS * KTOT; idx += NTHREADS) {
        int r = idx / KTOT;
        int k = idx - r * KTOT;
        int g = r >> 3, du = r & 7;
        int grow = g * HID + u0 + du;
        float v = (k < EMBD) ? W_ih[grow * EMBD + k]
                             : W_hh[grow * HID + (k - EMBD)];
        w_s[r * WPAD + k] = v;
    }
    if (tid < NROWS) {
        int g = tid >> 3, du = tid & 7;
        int grow = g * HID + u0 + du;
        bs[tid] = b_ih[grow] + b_hh[grow];
    }
    if (tid < NB) lenS[tid] = lengths[tid];
    __syncthreads();
    if (tid == 0) {
        int m = 1;
        for (int b = 0; b < NB; b++) m = max(m, lenS[b]);
        *mlS = m;
    }
    // zero h region of z (t=0)
    for (int i = tid; i < BPC * HID; i += NTHREADS) {
        int b = i >> 8, u = i & 255;
        z_s[b * ZPAD + EMBD + u] = 0.0f;
    }
    // gather xe(0)
    if (tid < BPC) {
        int tok = x[(bb0 + tid) * NT + 0];
        const float4* e = (const float4*)(emb + (long)tok * EMBD);
        float4* zr = (float4*)(z_s + tid * ZPAD);
        #pragma unroll
        for (int q = 0; q < EMBD / 4; q++) zr[q] = e[q];
    }
    __syncthreads();
    const int maxlen = *mlS;

    // shared base for asm addressing
    uint32_t sb;
    asm("{ .reg .u64 t; cvta.to.shared.u64 t, %1; cvt.u32.u64 %0, t; }"
        : "=r"(sb) : "l"(sm));
    const uint32_t ZOFF = (uint32_t)(NROWS * WPAD) * 4u;

    // GEMM mapping: 256 threads = 32 rows x 8 batch-slots; batches bp and bp+8
    const int row = tid >> 3;
    const int bp  = tid & 7;
    const uint32_t waddr0 = sb + (uint32_t)(row * WPAD) * 4u;
    const uint32_t zaddrA = sb + ZOFF + (uint32_t)(bp * ZPAD) * 4u;
    const uint32_t zaddrB = zaddrA + (uint32_t)(8 * ZPAD) * 4u;
    const float bias = bs[row];
    float* goutA = gs + row * BPC + bp;
    float* goutB = goutA + 8;

    // phase-2 mapping (tid < 128)
    const int du2 = tid >> 4;
    const int b2l = tid & 15;
    const int bg = bb0 + b2l;
    const int uu = u0 + (du2 & 7);
    const int mylen = lenS[bg];
    float c_r = 0.0f, h_r = 0.0f;

    // flag pointer for polling (warp 0: thread 'us' polls producer 'us' of my bsl group)
    volatile int* myflag = (tid < USLICE) ? &g_flag[bsl][tid] : 0;

    unsigned long long Aa, Ab;
    const unsigned long long bias_pk =
        (unsigned long long)__float_as_uint(bias);   // (bias, 0)

    // ---- prologue: acc = bias + W_ih . xe(0) ----
    Aa = bias_pk; Ab = bias_pk;
    #pragma unroll
    for (int k = 0; k < EMBD; k += 4) {
        unsigned long long W01, W23, Z01a, Z23a, Z01b, Z23b;
        LDS2U64(W01, W23, waddr0 + k * 4);
        LDS2U64(Z01a, Z23a, zaddrA + k * 4);
        LDS2U64(Z01b, Z23b, zaddrB + k * 4);
        FMA2(Aa, W01, Z01a); FMA2(Ab, W01, Z01b);
        FMA2(Aa, W23, Z23a); FMA2(Ab, W23, Z23b);
    }

    for (int t = 0; t < maxlen; t++) {
        if (t > 0) {
            // ---- wait for same-bsl producers to publish h(t-1) ----
            if (tid < USLICE) {
                if (*myflag < t) {
                    do { __nanosleep(64); } while (*myflag < t);
                }
            }
            __syncthreads();
            // ---- stage h(t-1): volatile (L1-bypassing) loads ----
            const float4* src = (const float4*)(g_H[t & 1] + bb0 * HID);
            #pragma unroll
            for (int i = 0; i < (BPC * HID / 4) / NTHREADS; i++) {
                int idx = i * NTHREADS + tid;
                float4 v;
                asm volatile("ld.volatile.global.v4.f32 {%0,%1,%2,%3}, [%4];"
                             : "=f"(v.x), "=f"(v.y), "=f"(v.z), "=f"(v.w)
                             : "l"(src + idx));
                int b = idx >> 6;
                int u4 = (idx & 63) * 4;
                *(float4*)(z_s + b * ZPAD + EMBD + u4) = v;
            }
            __syncthreads();
        }

        // ---- acc += W_hh . h  (k = 32..287), k-split f32x2 ----
        {
            const uint32_t wk  = waddr0 + EMBD * 4;
            const uint32_t zkA = zaddrA + EMBD * 4;
            const uint32_t zkB = zaddrB + EMBD * 4;
            #pragma unroll 4
            for (int k = 0; k < HID; k += 4) {
                unsigned long long W01, W23, Z01a, Z23a, Z01b, Z23b;
                LDS2U64(W01, W23, wk + k * 4);
                LDS2U64(Z01a, Z23a, zkA + k * 4);
                LDS2U64(Z01b, Z23b, zkB + k * 4);
                FMA2(Aa, W01, Z01a); FMA2(Ab, W01, Z01b);
                FMA2(Aa, W23, Z23a); FMA2(Ab, W23, Z23b);
            }
        }
        {
            float a_lo = __uint_as_float((uint32_t)Aa);
            float a_hi = __uint_as_float((uint32_t)(Aa >> 32));
            float b_lo = __uint_as_float((uint32_t)Ab);
            float b_hi = __uint_as_float((uint32_t)(Ab >> 32));
            *goutA = a_lo + a_hi;
            *goutB = b_lo + b_hi;
        }
        __syncthreads();

        // ---- phase 2: activations + state update (tid < 128) ----
        if (tid < 128) {
            float gi = gs[(0 * UPC + du2) * BPC + b2l];
            float gf = gs[(1 * UPC + du2) * BPC + b2l];
            float gg = gs[(2 * UPC + du2) * BPC + b2l];
            float go = gs[(3 * UPC + du2) * BPC + b2l];
            float iv = sigf(gi), fv = sigf(gf), gv = tanha(gg), ov = sigf(go);
            float cn = fmaf(fv, c_r, iv * gv);
            float hn = ov * tanha(cn);
            if (t < mylen) { c_r = cn; h_r = hn; }
            g_H[(t & 1) ^ 1][bg * HID + uu] = h_r;
        }
        __syncthreads();   // all g_H stores issued CTA-wide

        // ---- publish: this CTA finished step t ----
        if (tid == 0) {
            __threadfence();                 // release h stores to gpu scope
            g_flag[bsl][us] = t + 1;
        }

        if (t + 1 < maxlen) {
            // overlap with other CTAs: gather xe(t+1)
            if (tid < BPC) {
                int tok = x[(bb0 + tid) * NT + (t + 1)];
                const float4* e = (const float4*)(emb + (long)tok * EMBD);
                float4* zr = (float4*)(z_s + tid * ZPAD);
                #pragma unroll
                for (int q = 0; q < EMBD / 4; q++) zr[q] = e[q];
            }
            __syncthreads();
            // overlap: input-projection GEMM for t+1
            Aa = bias_pk; Ab = bias_pk;
            #pragma unroll
            for (int k = 0; k < EMBD; k += 4) {
                unsigned long long W01, W23, Z01a, Z23a, Z01b, Z23b;
                LDS2U64(W01, W23, waddr0 + k * 4);
                LDS2U64(Z01a, Z23a, zaddrA + k * 4);
                LDS2U64(Z01b, Z23b, zaddrB + k * 4);
                FMA2(Aa, W01, Z01a); FMA2(Ab, W01, Z01b);
                FMA2(Aa, W23, Z23a); FMA2(Ab, W23, Z23b);
            }
        }
    }

    if (tid < 128) out[bg * HID + uu] = h_r;
}

extern "C" void kernel_launch(void* const* d_in, const int* in_sizes, int n_in,
                              void* d_out, int out_size) {
    const int*   x       = (const int*)d_in[0];
    const int*   lengths = (const int*)d_in[1];
    const float* emb     = (const float*)d_in[2];
    const float* W_ih    = (const float*)d_in[3];
    const float* W_hh    = (const float*)d_in[4];
    const float* b_ih    = (const float*)d_in[5];
    const float* b_hh    = (const float*)d_in[6];
    float* out = (float*)d_out;

    const int smem_bytes =
        (NROWS * WPAD + BPC * ZPAD + NROWS * BPC + NROWS) * (int)sizeof(float)
        + (NB + 1) * (int)sizeof(int) + 32;

    cudaFuncSetAttribute(lstm_persist_kernel,
                         cudaFuncAttributeMaxDynamicSharedMemorySize, smem_bytes);

    lstm_init_kernel<<<1, 128>>>();
    lstm_persist_kernel<<<NCTA, NTHREADS, smem_bytes>>>(
        x, lengths, emb, W_ih, W_hh, b_ih, b_hh, out);
}